// round 10
// baseline (speedup 1.0000x reference)
#include <cuda_runtime.h>
#include <cstdint>

#define BB 2048
#define TT 512
#define KK 32
#define CH 32
#define FULLM 0xffffffffu

// 128 MB alpha-row scratch (device global; no allocation)
__device__ float g_alpha[(size_t)BB * TT * KK];

// ---- packed f32x2 helpers
__device__ __forceinline__ unsigned long long add2(unsigned long long a, unsigned long long b) {
    unsigned long long r; asm("add.rn.f32x2 %0,%1,%2;" : "=l"(r) : "l"(a), "l"(b)); return r;
}
__device__ __forceinline__ unsigned long long fma2(unsigned long long a, unsigned long long b, unsigned long long c) {
    unsigned long long r; asm("fma.rn.f32x2 %0,%1,%2,%3;" : "=l"(r) : "l"(a), "l"(b), "l"(c)); return r;
}
__device__ __forceinline__ float2 unpk(unsigned long long a) {
    float2 f; asm("mov.b64 {%0,%1},%2;" : "=f"(f.x), "=f"(f.y) : "l"(a)); return f;
}
__device__ __forceinline__ unsigned long long pk(float x, float y) {
    unsigned long long r; asm("mov.b64 %0,{%1,%2};" : "=l"(r) : "f"(x), "f"(y)); return r;
}

// bundled warp argmax: first-occurrence (lowest index wins ties); result in all lanes
__device__ __forceinline__ void wargmax(float v, int i, float& bv, int& bi) {
    bv = v; bi = i;
#pragma unroll
    for (int o = 16; o; o >>= 1) {
        float ov = __shfl_xor_sync(FULLM, bv, o);
        int   oi = __shfl_xor_sync(FULLM, bi, o);
        if (ov > bv || (ov == bv && oi < bi)) { bv = ov; bi = oi; }
    }
}

// ---- Viterbi forward step: value-only max, store alpha_{t-1} row to global
// r2[c]   = (row[4c..4c+3])     -> trc2[2c],   trc2[2c+1]
// r2[c+4] = (row[4c+16..4c+19]) -> trc2[2c+8], trc2[2c+9]
__device__ __forceinline__ void vstep(float* __restrict__ row,
                                      float p,
                                      const unsigned long long* __restrict__ trc2,
                                      float& alpha,
                                      float* __restrict__ galpha_prev_row,
                                      int lane)
{
    galpha_prev_row[lane] = alpha;   // alpha_{t-1}, needed by backtrace
    row[lane] = alpha;
    __syncwarp();
    const ulonglong2* r2 = reinterpret_cast<const ulonglong2*>(row);
    float best = -3.402823466e38f;
#pragma unroll
    for (int c = 0; c < 4; c++) {
        ulonglong2 qa = r2[c];
        ulonglong2 qb = r2[c + 4];
        float2 f0 = unpk(add2(qa.x, trc2[2 * c + 0]));
        float2 f1 = unpk(add2(qa.y, trc2[2 * c + 1]));
        float2 f2 = unpk(add2(qb.x, trc2[2 * c + 8]));
        float2 f3 = unpk(add2(qb.y, trc2[2 * c + 9]));
        float m0 = fmaxf(fmaxf(f0.x, f0.y), fmaxf(f1.x, f1.y));
        float m1 = fmaxf(fmaxf(f2.x, f2.y), fmaxf(f3.x, f3.y));
        best = fmaxf(best, fmaxf(m0, m1));
    }
    alpha = p + best;
}

// ---- linear-domain partition step: a_t[j] = exp(p_j) * sum_i E[i][j] * a_{t-1}[i]
// No max tree, no log. Positive sums only (well-conditioned).
__device__ __forceinline__ void lstep(float* __restrict__ row,
                                      float p,
                                      const unsigned long long* __restrict__ etr2,
                                      float& a, int lane)
{
    const float LOG2E = 1.4426950408889634f;
    row[lane] = a;
    float ep = exp2f(p * LOG2E);
    __syncwarp();
    const ulonglong2* r2 = reinterpret_cast<const ulonglong2*>(row);
    unsigned long long a0 = 0ull, a1 = 0ull, a2 = 0ull, a3 = 0ull;
#pragma unroll
    for (int c = 0; c < 4; c++) {
        ulonglong2 qa = r2[c];
        ulonglong2 qb = r2[c + 4];
        a0 = fma2(qa.x, etr2[2 * c + 0], a0);
        a1 = fma2(qa.y, etr2[2 * c + 1], a1);
        a2 = fma2(qb.x, etr2[2 * c + 8], a2);
        a3 = fma2(qb.y, etr2[2 * c + 9], a3);
    }
    float2 s = unpk(add2(add2(a0, a1), add2(a2, a3)));
    a = ep * (s.x + s.y);
}

// exact power-of-2 renormalization: scale all lanes by 2^-de (de = warp-max exponent)
__device__ __forceinline__ void renorm(float& a, int& C) {
    int eb = (__float_as_int(a) >> 23) & 0xff;   // biased exponent
#pragma unroll
    for (int o = 16; o; o >>= 1)
        eb = max(eb, __shfl_xor_sync(FULLM, eb, o));
    int de = eb - 127;
    C += de;
    a *= __int_as_float((127 - de) << 23);       // exact 2^-de
}

__global__ __launch_bounds__(64, 16)
void crf_fused_kernel(const float* __restrict__ pot,     // [B,T,K]
                      const float* __restrict__ trans,   // [K,K]
                      const int*   __restrict__ seqlen,  // [B]
                      const int*   __restrict__ tags_in, // [B,T]
                      float*       __restrict__ out)     // [B*T + 2B] f32
{
    __shared__ float Trp[KK * 33];                     // padded Tr for backtrace
    __shared__ __align__(16) float vrow[2][KK];
    __shared__ __align__(16) float lrow[2][KK];
    __shared__ float btrows[CH * KK];                  // backtrace alpha chunk

    const int tid  = threadIdx.x;
    const int lane = tid & 31;
    const int role = tid >> 5;          // 0 = viterbi, 1 = partition
    const int b    = blockIdx.x;
    const int len  = seqlen[b];

    const float LOG2E = 1.4426950408889634f;
    const float* pb = pot + (size_t)b * TT * KK;
    float* out_tags = out;

    // padded transitions into smem (both warps), needed by warp0's backtrace
    for (int idx = tid; idx < KK * KK; idx += 64)
        Trp[(idx >> 5) * 33 + (idx & 31)] = trans[idx];
    __syncthreads();

    if (role == 0) {
        // ===================== Viterbi warp =====================
        // packed Tr columns: trc2[k] = (Tr[2k][lane], Tr[2k+1][lane])
        unsigned long long trc2[16];
#pragma unroll
        for (int k = 0; k < 16; k++)
            trc2[k] = pk(__ldg(&trans[(2 * k) * KK + lane]),
                         __ldg(&trans[(2 * k + 1) * KK + lane]));

        float* gab = g_alpha + (size_t)b * TT * KK;
        float alpha = pb[lane];

        int t = 1;
        for (; t + 1 < len; t += 2) {
            float pa = pb[(size_t)t * KK + lane];
            float pc = pb[(size_t)(t + 1) * KK + lane];
            vstep(vrow[0], pa, trc2, alpha, gab + (size_t)(t - 1) * KK, lane);
            vstep(vrow[1], pc, trc2, alpha, gab + (size_t)t * KK, lane);
        }
        if (t < len) {
            float pa = pb[(size_t)t * KK + lane];
            vstep(vrow[0], pa, trc2, alpha, gab + (size_t)(t - 1) * KK, lane);
        }

        // last_tag / best_score
        float bv; int bi;
        wargmax(alpha, lane, bv, bi);
        const int last_tag = bi;

        for (int tt = len - 1 + lane; tt < TT; tt += 32)
            out_tags[(size_t)b * TT + tt] = (float)last_tag;
        if (lane == 0)
            out[(size_t)BB * TT + b] = bv;   // best_score

        // make alpha-row STGs visible before backtrace reads
        __threadfence_block();
        __syncwarp(FULLM);

        // ---- backtrace: chunk alpha rows into smem, warp-cooperative argmax
        int j  = last_tag;
        int hi = len - 2;
        while (hi >= 0) {
            int lo = hi - (CH - 1); if (lo < 0) lo = 0;
            int n  = (hi - lo + 1) * KK;
            for (int k = lane; k < n; k += 32)
                btrows[k] = gab[(size_t)lo * KK + k];
            __syncwarp(FULLM);
            for (int tt = hi; tt >= lo; tt--) {
                float s = btrows[(tt - lo) * KK + lane] + Trp[lane * 33 + j];
                float mv; int mi;
                wargmax(s, lane, mv, mi);
                j = mi;
                if (lane == 0)
                    out_tags[(size_t)b * TT + tt] = (float)j;
            }
            __syncwarp(FULLM);
            hi = lo - 1;
        }
    } else {
        // ============ partition (linear domain) + seq-score warp ============
        // etr2[k] = (exp(Tr[2k][lane]), exp(Tr[2k+1][lane]))
        unsigned long long etr2[16];
#pragma unroll
        for (int k = 0; k < 16; k++)
            etr2[k] = pk(exp2f(__ldg(&trans[(2 * k) * KK + lane]) * LOG2E),
                         exp2f(__ldg(&trans[(2 * k + 1) * KK + lane]) * LOG2E));

        float a = exp2f(pb[lane] * LOG2E);   // a_0 = exp(pot_0)
        int C = 0;                           // accumulated power-of-2 exponent

        int t = 1;
        for (; t + 1 < len; t += 2) {
            float pa = pb[(size_t)t * KK + lane];
            float pc = pb[(size_t)(t + 1) * KK + lane];
            lstep(lrow[0], pa, etr2, a, lane);
            lstep(lrow[1], pc, etr2, a, lane);
            if (((t + 1) & 7) == 0)          // after steps 8, 16, 24, ...
                renorm(a, C);
        }
        if (t < len) {
            float pa = pb[(size_t)t * KK + lane];
            lstep(lrow[0], pa, etr2, a, lane);
        }

        // log_norm = C*ln2 + log(sum_j a_j)
        float s = a;
#pragma unroll
        for (int o = 16; o; o >>= 1)
            s += __shfl_xor_sync(FULLM, s, o);
        float log_norm = (float)((double)C * 0.6931471805599453) + logf(s);

        // sequence score (gold path)
        const int* ti = tags_in + (size_t)b * TT;
        float sscore = 0.f;
        for (int tt = lane; tt < TT; tt += 32) {
            int tg = ti[tt];
            if (tt < len)     sscore += pb[(size_t)tt * KK + tg];
            if (tt < len - 1) sscore += __ldg(&trans[tg * KK + ti[tt + 1]]);
        }
#pragma unroll
        for (int o = 16; o; o >>= 1)
            sscore += __shfl_xor_sync(FULLM, sscore, o);

        if (lane == 0)
            out[(size_t)BB * TT + BB + b] = sscore - log_norm;
    }
}

extern "C" void kernel_launch(void* const* d_in, const int* in_sizes, int n_in,
                              void* d_out, int out_size) {
    const float* pot    = (const float*)d_in[0];
    const float* trans  = (const float*)d_in[1];
    const int*   seqlen = (const int*)d_in[2];
    const int*   tags   = (const int*)d_in[3];
    float* out = (float*)d_out;

    // one sequence per 64-thread block (viterbi warp + partition warp)
    crf_fused_kernel<<<BB, 64>>>(pot, trans, seqlen, tags, out);
}